// round 8
// baseline (speedup 1.0000x reference)
#include <cuda_runtime.h>
#include <cstdint>

// Problem constants
#define CCk 128
#define DDk 32
#define SSk 4096

// ---------------- smem byte layout ----------------
// 4 stage buffers of 32KB: stage i at i*32KB (group g owns stages {2g, 2g+1}).
//   Each stage: hi [128 rows][64 cols] bf16 (16KB) + lo (+16KB).
// E partials (f32 [128][132]): E1 at 0, E2 at 67584 — alias dead stages
//   (valid: global __syncthreads separates stage use from E use).
// A_hi (bf16 K-major, two 16KB blocks by m>>6) at 135168.
// inv[128] f32 at 167936.
#define STG(i)   ((uint32_t)(i) * 32768u)
#define ESTR     132
#define E2OFF    67584u
#define AOFF     135168u
#define IVOFF    167936u
#define SMEMSZ   (IVOFF + 512u)

#define SWZ(o) ((o) ^ (((o) >> 3) & 0x70u))
#define GBAR(g) asm volatile("bar.sync %0, 256;" :: "r"((g) + 1) : "memory")

static __device__ __forceinline__ uint32_t s2u(const void* p) {
    uint32_t a;
    asm("{ .reg .u64 t; cvta.to.shared.u64 t, %1; cvt.u32.u64 %0, t; }"
        : "=r"(a) : "l"(p));
    return a;
}

static __device__ __forceinline__ void ldsm4(uint32_t* r, uint32_t addr) {
    asm volatile("ldmatrix.sync.aligned.m8n8.x4.shared.b16 {%0,%1,%2,%3}, [%4];"
        : "=r"(r[0]), "=r"(r[1]), "=r"(r[2]), "=r"(r[3]) : "r"(addr));
}
static __device__ __forceinline__ void ldsm4t(uint32_t* r, uint32_t addr) {
    asm volatile("ldmatrix.sync.aligned.m8n8.x4.trans.shared.b16 {%0,%1,%2,%3}, [%4];"
        : "=r"(r[0]), "=r"(r[1]), "=r"(r[2]), "=r"(r[3]) : "r"(addr));
}
static __device__ __forceinline__ void mma16816(float* c, const uint32_t* a,
                                                uint32_t b0, uint32_t b1) {
    asm volatile(
        "mma.sync.aligned.m16n8k16.row.col.f32.bf16.bf16.f32 "
        "{%0,%1,%2,%3}, {%4,%5,%6,%7}, {%8,%9}, {%0,%1,%2,%3};"
        : "+f"(c[0]), "+f"(c[1]), "+f"(c[2]), "+f"(c[3])
        : "r"(a[0]), "r"(a[1]), "r"(a[2]), "r"(a[3]), "r"(b0), "r"(b1));
}

static __device__ __forceinline__ void split2(float f0, float f1, uint32_t& hp, uint32_t& lp) {
    asm("cvt.rn.bf16x2.f32 %0, %1, %2;" : "=r"(hp) : "f"(f1), "f"(f0));
    float h0 = __uint_as_float(hp << 16);
    float h1 = __uint_as_float(hp & 0xffff0000u);
    asm("cvt.rn.bf16x2.f32 %0, %1, %2;" : "=r"(lp) : "f"(f1 - h1), "f"(f0 - h0));
}
static __device__ __forceinline__ uint32_t pack2hi(float f0, float f1) {
    uint32_t hp;
    asm("cvt.rn.bf16x2.f32 %0, %1, %2;" : "=r"(hp) : "f"(f1), "f"(f0));
    return hp;
}
static __device__ __forceinline__ void split8(float4 a, float4 b, uint4& hi, uint4& lo) {
    split2(a.x, a.y, hi.x, lo.x);
    split2(a.z, a.w, hi.y, lo.y);
    split2(b.x, b.y, hi.z, lo.z);
    split2(b.z, b.w, hi.w, lo.w);
}
static __device__ __forceinline__ float2 bfpair(uint32_t w) {
    float2 r;
    r.x = __uint_as_float(w << 16);
    r.y = __uint_as_float(w & 0xffff0000u);
    return r;
}

__global__ __launch_bounds__(512, 1)
void cam_mma4_kernel(const float* __restrict__ x,
                     const float* __restrict__ gamma,
                     float* __restrict__ out)
{
    extern __shared__ __align__(1024) uint8_t sm[];
    const uint32_t smb = s2u(sm);

    const int tid  = threadIdx.x;
    const int lane = tid & 31;
    const int wid  = tid >> 5;
    const int grp  = wid >> 3;        // 0 or 1: independent 8-warp group
    const int sub  = wid & 7;
    const int wm   = sub & 3;
    const int wn   = sub >> 2;        // 0 or 1
    const int m0   = wm * 32;
    const int n0   = wn * 64;

    const int n = blockIdx.x;
    const int b = n / DDk, d = n % DDk;
    const float* xbase = x + ((size_t)(b * CCk) * DDk + d) * (size_t)SSk;
    const size_t cstride = (size_t)DDk * SSk;
    float* outbase = out + (size_t)n * CCk * SSk;

    // conversion mapping within a group: 256 threads -> 128 rows x 2 halves
    const int gtid = tid & 255;
    const int r = gtid >> 1, h = gtid & 1;
    const float* rowp = xbase + (size_t)r * cstride;

    // =============== Phase 1: E = V*V^T, k-chunks split even/odd by group ===============
    float acc[2][8][4];
#pragma unroll
    for (int mt = 0; mt < 2; mt++)
#pragma unroll
        for (int nt = 0; nt < 8; nt++)
#pragma unroll
            for (int q = 0; q < 4; q++) acc[mt][nt][q] = 0.f;

    for (int kc = grp; kc < 64; kc += 2) {
        const int slot = grp * 2 + ((kc >> 1) & 1);
        uint8_t* hb = sm + STG(slot);
        uint8_t* lb = hb + 16384;
        const float* src = rowp + kc * 64 + h * 32;
#pragma unroll
        for (int g2 = 0; g2 < 4; g2++) {
            float4 f0 = *reinterpret_cast<const float4*>(src + g2 * 8);
            float4 f1 = *reinterpret_cast<const float4*>(src + g2 * 8 + 4);
            uint4 hi4, lo4;
            split8(f0, f1, hi4, lo4);
            uint32_t off = SWZ((uint32_t)(r * 128 + h * 64 + g2 * 16));
            *reinterpret_cast<uint4*>(hb + off) = hi4;
            *reinterpret_cast<uint4*>(lb + off) = lo4;
        }
        GBAR(grp);
        const uint32_t hbu = smb + STG(slot);
        const uint32_t lbu = hbu + 16384u;
#pragma unroll
        for (int kk = 0; kk < 4; kk++) {
            uint32_t ah[2][4], al[2][4];
#pragma unroll
            for (int mt = 0; mt < 2; mt++) {
                int rowA = m0 + mt * 16 + (lane & 15);
                int ch = kk * 2 + (lane >> 4);
                uint32_t off = SWZ((uint32_t)(rowA * 128 + ch * 16));
                ldsm4(ah[mt], hbu + off);
                ldsm4(al[mt], lbu + off);
            }
#pragma unroll
            for (int bt = 0; bt < 4; bt++) {
                uint32_t bh[4], bl[4];
                int rowB = n0 + bt * 16 + ((lane >> 4) & 1) * 8 + (lane & 7);
                int ch = kk * 2 + ((lane >> 3) & 1);
                uint32_t off = SWZ((uint32_t)(rowB * 128 + ch * 16));
                ldsm4(bh, hbu + off);
                ldsm4(bl, lbu + off);
#pragma unroll
                for (int mt = 0; mt < 2; mt++)
#pragma unroll
                    for (int nn = 0; nn < 2; nn++) {
                        float* a4 = acc[mt][bt * 2 + nn];
                        mma16816(a4, ah[mt], bh[nn * 2], bh[nn * 2 + 1]);
                        mma16816(a4, ah[mt], bl[nn * 2], bl[nn * 2 + 1]);
                        mma16816(a4, al[mt], bh[nn * 2], bh[nn * 2 + 1]);
                    }
            }
        }
    }

    __syncthreads();   // all stages dead; E regions may alias them now

    // spill partial E (group g -> its own region)
    {
        float* E = reinterpret_cast<float*>(sm + (grp ? E2OFF : 0u));
#pragma unroll
        for (int mt = 0; mt < 2; mt++)
#pragma unroll
            for (int nt = 0; nt < 8; nt++) {
                int row = m0 + mt * 16 + (lane >> 2);
                int col = n0 + nt * 8 + (lane & 3) * 2;
                *reinterpret_cast<float2*>(&E[row * ESTR + col]) =
                    make_float2(acc[mt][nt][0], acc[mt][nt][1]);
                *reinterpret_cast<float2*>(&E[(row + 8) * ESTR + col]) =
                    make_float2(acc[mt][nt][2], acc[mt][nt][3]);
            }
    }
    __syncthreads();

    // =============== Softmin (E = E1 + E2): A_hi[c][m] = bf16(exp(min - E)) ===============
    if (tid < 128) {
        const int c = tid;
        const float* E1 = reinterpret_cast<const float*>(sm) + c * ESTR;
        const float* E2 = reinterpret_cast<const float*>(sm + E2OFF) + c * ESTR;
        float mn = 3.4e38f;
#pragma unroll 4
        for (int m = 0; m < 128; m++) mn = fminf(mn, E1[m] + E2[m]);
        float sum = 0.f;
#pragma unroll
        for (int mg = 0; mg < 16; mg++) {
            float p[8];
#pragma unroll
            for (int q = 0; q < 8; q++) {
                p[q] = __expf(mn - (E1[mg * 8 + q] + E2[mg * 8 + q]));
                sum += p[q];
            }
            uint4 hi4;
            hi4.x = pack2hi(p[0], p[1]);
            hi4.y = pack2hi(p[2], p[3]);
            hi4.z = pack2hi(p[4], p[5]);
            hi4.w = pack2hi(p[6], p[7]);
            const int m = mg * 8;
            uint32_t off = AOFF + (uint32_t)(m >> 6) * 16384u
                         + SWZ((uint32_t)(c * 128 + (m & 63) * 2));
            *reinterpret_cast<uint4*>(sm + off) = hi4;
        }
        reinterpret_cast<float*>(sm + IVOFF)[c] = gamma[0] / sum;
    }
    __syncthreads();

    // =============== Phase 2: out = A_hi * V_hi; s-chunks split even/odd by group ===============
    uint32_t ahr[2][8][4];
#pragma unroll
    for (int mt = 0; mt < 2; mt++)
#pragma unroll
        for (int kk = 0; kk < 8; kk++) {
            int rowA = m0 + mt * 16 + (lane & 15);
            int chb = (kk & 3) * 2 + (lane >> 4);
            uint32_t off = AOFF + (uint32_t)(kk >> 2) * 16384u
                         + SWZ((uint32_t)(rowA * 128 + chb * 16));
            ldsm4(ahr[mt][kk], smb + off);
        }

    const float* ivp = reinterpret_cast<const float*>(sm + IVOFF);

    for (int sc = grp; sc < 64; sc += 2) {
        const int slot = grp * 2 + ((sc >> 1) & 1);
        uint8_t* hb = sm + STG(slot);
        uint8_t* lb = hb + 16384;
        const float* src = rowp + sc * 64 + h * 32;
#pragma unroll
        for (int g2 = 0; g2 < 4; g2++) {
            float4 f0 = *reinterpret_cast<const float4*>(src + g2 * 8);
            float4 f1 = *reinterpret_cast<const float4*>(src + g2 * 8 + 4);
            uint4 hi4, lo4;
            split8(f0, f1, hi4, lo4);
            uint32_t off = SWZ((uint32_t)(r * 128 + h * 64 + g2 * 16));
            *reinterpret_cast<uint4*>(hb + off) = hi4;
            *reinterpret_cast<uint4*>(lb + off) = lo4;
        }
        GBAR(grp);

        float c2[2][4][4];
#pragma unroll
        for (int mt = 0; mt < 2; mt++)
#pragma unroll
            for (int nt = 0; nt < 4; nt++)
#pragma unroll
                for (int q = 0; q < 4; q++) c2[mt][nt][q] = 0.f;

        const uint32_t Bh = smb + STG(slot);
#pragma unroll
        for (int kk = 0; kk < 8; kk++) {
            uint32_t bh[2][4];
#pragma unroll
            for (int bt = 0; bt < 2; bt++) {
                int rowB = kk * 16 + (lane & 15);
                int sch = wn * 4 + bt * 2 + (lane >> 4);
                uint32_t off = SWZ((uint32_t)(rowB * 128 + sch * 16));
                ldsm4t(bh[bt], Bh + off);
            }
#pragma unroll
            for (int mt = 0; mt < 2; mt++)
#pragma unroll
                for (int nt = 0; nt < 4; nt++)
                    mma16816(c2[mt][nt], ahr[mt][kk],
                             bh[nt >> 1][(nt & 1) * 2], bh[nt >> 1][(nt & 1) * 2 + 1]);
        }

        // epilogue: out[c][s] = inv[c]*acc + V[c][s]  (V = hi + lo from stage)
#pragma unroll
        for (int mt = 0; mt < 2; mt++)
#pragma unroll
            for (int nt = 0; nt < 4; nt++) {
                int row = m0 + mt * 16 + (lane >> 2);
                int scol = wn * 32 + nt * 8 + (lane & 3) * 2;
#pragma unroll
                for (int half = 0; half < 2; half++) {
                    int c = row + half * 8;
                    float iv = ivp[c];
                    uint32_t offv = SWZ((uint32_t)(c * 128 + scol * 2));
                    float2 vh = bfpair(*reinterpret_cast<const uint32_t*>(hb + offv));
                    float2 vl = bfpair(*reinterpret_cast<const uint32_t*>(lb + offv));
                    float2 o;
                    o.x = fmaf(c2[mt][nt][half * 2 + 0], iv, vh.x + vl.x);
                    o.y = fmaf(c2[mt][nt][half * 2 + 1], iv, vh.y + vl.y);
                    *reinterpret_cast<float2*>(outbase + (size_t)c * SSk + sc * 64 + scol) = o;
                }
            }
    }
}

extern "C" void kernel_launch(void* const* d_in, const int* in_sizes, int n_in,
                              void* d_out, int out_size)
{
    const float* x     = (const float*)d_in[0];
    const float* gamma = (const float*)d_in[1];
    float* out = (float*)d_out;

    cudaFuncSetAttribute(cam_mma4_kernel,
                         cudaFuncAttributeMaxDynamicSharedMemorySize, SMEMSZ);
    cam_mma4_kernel<<<128, 512, SMEMSZ>>>(x, gamma, out);
}